// round 17
// baseline (speedup 1.0000x reference)
#include <cuda_runtime.h>

// DelayBuffer: out[b, t, i*D + c] = emb[b, t - d_i, c] if t >= d_i else emb[b, t, c]
// d_i in (1, 2, 4, 8, 16, 32) = 1 << i
// B=4, S=4096, D=1024 (fp32). Output [B, S, 6*D].
//
// R9 gather structure with 256-bit streaming stores (st.global.cs.v4.b64):
//   - block = 256 threads = two t-rows; each thread owns one 32 B chunk
//   - per thread: 12 front-batched 16 B __ldg loads (proven full-rate path;
//     input is L2-resident across replays), then 6 x 32 B evict-first stores
//   - halves STG count / L2 store requests vs R9; tests whether wider store
//     bursts raise DRAM write efficiency past the observed 5.9 TB/s.

static constexpr int B    = 4;
static constexpr int S    = 4096;
static constexpr int D    = 1024;
static constexpr int D4   = D / 4;        // 256 float4 per segment
static constexpr int ND   = 6;            // number of delays
static constexpr int C8   = D / 8;        // 128 x 32B chunks per segment
static constexpr int ROW4 = ND * D4;      // output row width in float4 (1536)

__device__ __forceinline__ void stcs_256(void* p, ulonglong2 lo, ulonglong2 hi) {
    asm volatile("st.global.cs.v4.b64 [%0], {%1, %2, %3, %4};"
                 :: "l"(p), "l"(lo.x), "l"(lo.y), "l"(hi.x), "l"(hi.y)
                 : "memory");
}

__global__ __launch_bounds__(256)
void delay_buffer_kernel(const float4* __restrict__ in, float4* __restrict__ out) {
    const int c8 = threadIdx.x & (C8 - 1);   // 0..127: which 32B chunk of a row
    const int j  = threadIdx.x >> 7;         // 0..1: which of the two rows
    const int t  = blockIdx.x * 2 + j;       // 0..4095
    const int b  = blockIdx.y;               // 0..3

    const ulonglong2* const ibat = (const ulonglong2*)(in + (size_t)b * S * D4);

    // 12 independent 16B loads (6 chunk-pairs), front-batched for MLP
    ulonglong2 lo[ND], hi[ND];
#pragma unroll
    for (int i = 0; i < ND; i++) {
        const int d = 1 << i;                     // DELAYS = (1,2,4,8,16,32)
        const int src_t = (t >= d) ? (t - d) : t;
        const ulonglong2* p = ibat + (size_t)src_t * C8 * 2 + 2 * c8;
        lo[i] = __ldg(p);
        hi[i] = __ldg(p + 1);
    }

    // 6 x 32B streaming stores into the contiguous output row [row, 6*D]
    float4* orow = out + (size_t)(b * S + t) * ROW4 + 2 * c8;
#pragma unroll
    for (int i = 0; i < ND; i++) {
        stcs_256(orow + i * D4, lo[i], hi[i]);
    }
}

extern "C" void kernel_launch(void* const* d_in, const int* in_sizes, int n_in,
                              void* d_out, int out_size) {
    const float4* in = (const float4*)d_in[0];
    float4* out = (float4*)d_out;

    dim3 grid(S / 2, B);
    delay_buffer_kernel<<<grid, 256>>>(in, out);
}